// round 11
// baseline (speedup 1.0000x reference)
#include <cuda_runtime.h>
#include <cuda_fp16.h>

#define N_NODES 100000
#define E_CAP   2000000
#define HID 64
#define EPS 1e-5f

#define SCAN_CHUNK 1024
#define SCAN_NBLK  ((N_NODES + SCAN_CHUNK - 1) / SCAN_CHUNK)   // 98

// Scratch (allocation-free rule: __device__ globals)
__device__ float  g_dinv[N_NODES];             // rsqrt(1+deg)
__device__ int    g_degi[N_NODES];             // int in-degree (no self loop)
__device__ int    g_cur [N_NODES];             // fill cursors
__device__ int    g_rowptr[N_NODES + 1];       // CSR row pointers (by dst)
__device__ int    g_csr[E_CAP];                // CSR src indices
__device__ int    g_blocksum[SCAN_NBLK];       // scan phase-1 partials
__device__ int    g_blockoff[SCAN_NBLK];       // scan phase-2 offsets
__device__ __half g_ph [N_NODES * HID];        // p = (act(h) @ W) * dinv[row], fp16
__device__ float  g_agg[N_NODES * HID];        // aggregated (pre-BN), next-layer input
__device__ float  g_stats[2 * HID];            // per-channel sum / sumsq
__device__ float  g_bnc[2 * HID];              // per-channel BN (scale, shift)

// ---------------- degree / CSR build ----------------
__global__ void k_zero_idx() {
    int i = blockIdx.x * blockDim.x + threadIdx.x;
    if (i < N_NODES) { g_degi[i] = 0; g_cur[i] = 0; }
    if (i < 2 * HID) g_stats[i] = 0.0f;
}

__global__ void k_count_deg(const int* __restrict__ dst, int E) {
    int i = blockIdx.x * blockDim.x + threadIdx.x;
    if (i < E) atomicAdd(&g_degi[dst[i]], 1);
}

__global__ void k_finish_deg() {
    int i = blockIdx.x * blockDim.x + threadIdx.x;
    if (i < N_NODES) g_dinv[i] = rsqrtf((float)(1 + g_degi[i]));   // self loop
}

// ---- 3-phase device-wide exclusive scan of g_degi -> g_rowptr ----
__global__ void k_scan_p1() {
    __shared__ int red[256];
    int t = threadIdx.x;
    int base = blockIdx.x * SCAN_CHUNK + t * 4;
    int s = 0;
#pragma unroll
    for (int i = 0; i < 4; i++) {
        int idx = base + i;
        if (idx < N_NODES) s += g_degi[idx];
    }
    red[t] = s;
    __syncthreads();
    for (int off = 128; off > 0; off >>= 1) {
        if (t < off) red[t] += red[t + off];
        __syncthreads();
    }
    if (t == 0) g_blocksum[blockIdx.x] = red[0];
}

__global__ void k_scan_p2() {
    __shared__ int s[SCAN_NBLK];
    int t = threadIdx.x;
    if (t < SCAN_NBLK) s[t] = g_blocksum[t];
    __syncthreads();
    if (t == 0) {
        int run = 0;
        for (int i = 0; i < SCAN_NBLK; i++) { int v = s[i]; s[i] = run; run += v; }
    }
    __syncthreads();
    if (t < SCAN_NBLK) g_blockoff[t] = s[t];
}

__global__ void k_scan_p3(int E) {
    __shared__ int ssum[256];
    int t = threadIdx.x;
    int base = blockIdx.x * SCAN_CHUNK + t * 4;
    int d[4];
    int s = 0;
#pragma unroll
    for (int i = 0; i < 4; i++) {
        int idx = base + i;
        d[i] = (idx < N_NODES) ? g_degi[idx] : 0;
        s += d[i];
    }
    ssum[t] = s;
    __syncthreads();
    for (int off = 1; off < 256; off <<= 1) {
        int v = (t >= off) ? ssum[t - off] : 0;
        __syncthreads();
        ssum[t] += v;
        __syncthreads();
    }
    int run = g_blockoff[blockIdx.x] + ((t == 0) ? 0 : ssum[t - 1]);
#pragma unroll
    for (int i = 0; i < 4; i++) {
        int idx = base + i;
        if (idx < N_NODES) { g_rowptr[idx] = run; run += d[i]; }
    }
    if (blockIdx.x == gridDim.x - 1 && t == 255) g_rowptr[N_NODES] = E;
}

__global__ void k_fill(const int* __restrict__ src, const int* __restrict__ dst, int E) {
    int e = blockIdx.x * blockDim.x + threadIdx.x;
    if (e >= E) return;
    int d = dst[e];
    int pos = atomicAdd(&g_cur[d], 1);
    g_csr[g_rowptr[d] + pos] = src[e];
}

// ---------------- fused GEMM (double-buffered, prefetch) -------------------
// p = act(in) @ W * dinv[row], stored fp16 to g_ph.
// act = identity (layer 0, in = x) or BN+ReLU via g_bnc (layers 1,2, in = g_agg).
// BM=128, BN=64, BK=16. 256 threads, 4x8 microtile.
__global__ void __launch_bounds__(256, 2)
k_gemm_fused(const float* __restrict__ xin, const float* __restrict__ W,
             int fi, int use_bn)
{
    __shared__ float sA[2][128 * 20];   // [buf][row*20 + k], pad 16->20
    __shared__ float sW[2][16 * 64];    // [buf][k*64 + col]
    __shared__ float sDinv[128];
    __shared__ float sSc[64], sSh[64];

    const float* in = use_bn ? (const float*)g_agg : xin;

    int tid = threadIdx.x;
    int block_row = blockIdx.x * 128;

    if (use_bn && tid < 64) { sSc[tid] = g_bnc[tid]; sSh[tid] = g_bnc[64 + tid]; }
    if (tid < 128) {
        int r = block_row + tid;
        sDinv[tid] = (r < N_NODES) ? g_dinv[r] : 0.0f;
    }

    // load assignments
    int rowA = tid >> 2;            // 0..63 (+64 for 2nd element)
    int colA = (tid & 3) * 4;       // k-offset within tile (0,4,8,12)
    int rowW = tid >> 4;            // 0..15
    int colW = (tid & 15) * 4;

    int ty = tid >> 3;              // 0..31 -> rows ty*4..+4
    int tx = tid & 7;               // 0..7  -> cols tx*8..+8

    float4 ra[2], rw;

    auto loadTile = [&](int k0) {
#pragma unroll
        for (int i = 0; i < 2; i++) {
            int rg = block_row + rowA + i * 64;
            ra[i] = (rg < N_NODES) ? *(const float4*)(in + (size_t)rg * fi + k0 + colA)
                                   : make_float4(0.f, 0.f, 0.f, 0.f);
        }
        rw = *(const float4*)(W + (size_t)(k0 + rowW) * 64 + colW);
    };
    auto storeTile = [&](int buf, int k0) {
        if (use_bn) {
            int c = k0 + colA;
#pragma unroll
            for (int i = 0; i < 2; i++) {
                ra[i].x = fmaxf(ra[i].x * sSc[c]     + sSh[c],     0.f);
                ra[i].y = fmaxf(ra[i].y * sSc[c + 1] + sSh[c + 1], 0.f);
                ra[i].z = fmaxf(ra[i].z * sSc[c + 2] + sSh[c + 2], 0.f);
                ra[i].w = fmaxf(ra[i].w * sSc[c + 3] + sSh[c + 3], 0.f);
            }
        }
#pragma unroll
        for (int i = 0; i < 2; i++)
            *(float4*)(&sA[buf][(rowA + i * 64) * 20 + colA]) = ra[i];
        *(float4*)(&sW[buf][rowW * 64 + colW]) = rw;
    };

    float acc[4][8];
#pragma unroll
    for (int i = 0; i < 4; i++)
#pragma unroll
        for (int j = 0; j < 8; j++) acc[i][j] = 0.0f;

    int nt = fi >> 4;

    loadTile(0);
    __syncthreads();            // sSc/sSh/sDinv ready (needed by storeTile/epilogue)
    storeTile(0, 0);
    __syncthreads();

    for (int t = 0; t < nt; t++) {
        int cur = t & 1;
        if (t + 1 < nt) loadTile((t + 1) << 4);

#pragma unroll
        for (int k = 0; k < 16; k++) {
            float4 b0 = *(const float4*)(&sW[cur][k * 64 + tx * 8]);
            float4 b1 = *(const float4*)(&sW[cur][k * 64 + tx * 8 + 4]);
            float a0 = sA[cur][(ty * 4 + 0) * 20 + k];
            float a1 = sA[cur][(ty * 4 + 1) * 20 + k];
            float a2 = sA[cur][(ty * 4 + 2) * 20 + k];
            float a3 = sA[cur][(ty * 4 + 3) * 20 + k];
            acc[0][0] += a0 * b0.x; acc[0][1] += a0 * b0.y; acc[0][2] += a0 * b0.z; acc[0][3] += a0 * b0.w;
            acc[0][4] += a0 * b1.x; acc[0][5] += a0 * b1.y; acc[0][6] += a0 * b1.z; acc[0][7] += a0 * b1.w;
            acc[1][0] += a1 * b0.x; acc[1][1] += a1 * b0.y; acc[1][2] += a1 * b0.z; acc[1][3] += a1 * b0.w;
            acc[1][4] += a1 * b1.x; acc[1][5] += a1 * b1.y; acc[1][6] += a1 * b1.z; acc[1][7] += a1 * b1.w;
            acc[2][0] += a2 * b0.x; acc[2][1] += a2 * b0.y; acc[2][2] += a2 * b0.z; acc[2][3] += a2 * b0.w;
            acc[2][4] += a2 * b1.x; acc[2][5] += a2 * b1.y; acc[2][6] += a2 * b1.z; acc[2][7] += a2 * b1.w;
            acc[3][0] += a3 * b0.x; acc[3][1] += a3 * b0.y; acc[3][2] += a3 * b0.z; acc[3][3] += a3 * b0.w;
            acc[3][4] += a3 * b1.x; acc[3][5] += a3 * b1.y; acc[3][6] += a3 * b1.z; acc[3][7] += a3 * b1.w;
        }

        if (t + 1 < nt) {
            storeTile(1 - cur, (t + 1) << 4);
            __syncthreads();
        }
    }

    // epilogue: g_ph = fp16( hw * dinv[row] )
#pragma unroll
    for (int i = 0; i < 4; i++) {
        int r = block_row + ty * 4 + i;
        if (r >= N_NODES) continue;
        float dv = sDinv[ty * 4 + i];
        __half2 h[4];
        h[0] = __floats2half2_rn(acc[i][0] * dv, acc[i][1] * dv);
        h[1] = __floats2half2_rn(acc[i][2] * dv, acc[i][3] * dv);
        h[2] = __floats2half2_rn(acc[i][4] * dv, acc[i][5] * dv);
        h[3] = __floats2half2_rn(acc[i][6] * dv, acc[i][7] * dv);
        *(uint4*)(g_ph + (size_t)r * HID + tx * 8) = *(uint4*)h;
    }
}

// ---------------- CSR aggregation + fused BN stats ------------------------
// agg[d] = bias + dinv[d] * ( sum_{s in in(d)} p[s] + p[d] ); stats += agg.
// Warp per node: 4 quarters x 8 lanes; lane handles 8 channels (16B fp16).
__global__ void __launch_bounds__(256)
k_aggregate(const float* __restrict__ bias) {
    __shared__ float ssum[64], ssq[64];
    int tid = threadIdx.x;
    if (tid < 64) { ssum[tid] = 0.f; ssq[tid] = 0.f; }
    __syncthreads();

    int warp = (blockIdx.x * 256 + tid) >> 5;
    int lane = tid & 31;
    int q = lane >> 3;          // quarter 0..3 (edge stride 4)
    int l = lane & 7;           // channel slice: l*8 .. l*8+7

    float acc[8];
#pragma unroll
    for (int i = 0; i < 8; i++) acc[i] = 0.f;

    if (warp < N_NODES) {
        int d = warp;
        int beg = g_rowptr[d], end = g_rowptr[d + 1];
        if (q == 0) {           // self loop
            uint4 u = *(const uint4*)(g_ph + (size_t)d * HID + l * 8);
            const __half2* h = (const __half2*)&u;
#pragma unroll
            for (int i = 0; i < 4; i++) {
                float2 f = __half22float2(h[i]);
                acc[2 * i] += f.x; acc[2 * i + 1] += f.y;
            }
        }
        for (int e = beg + q; e < end; e += 4) {
            int s = g_csr[e];
            uint4 u = *(const uint4*)(g_ph + (size_t)s * HID + l * 8);
            const __half2* h = (const __half2*)&u;
#pragma unroll
            for (int i = 0; i < 4; i++) {
                float2 f = __half22float2(h[i]);
                acc[2 * i] += f.x; acc[2 * i + 1] += f.y;
            }
        }
    }

    // combine quarters: lanes 0-15 += 16-31, then 0-7 += 8-15
#pragma unroll
    for (int i = 0; i < 8; i++) acc[i] += __shfl_down_sync(0xffffffffu, acc[i], 16);
#pragma unroll
    for (int i = 0; i < 8; i++) acc[i] += __shfl_down_sync(0xffffffffu, acc[i], 8);

    if (warp < N_NODES && q == 0) {
        float dv = g_dinv[warp];
        float r[8];
#pragma unroll
        for (int i = 0; i < 8; i++) r[i] = bias[l * 8 + i] + dv * acc[i];
        float* ag = g_agg + (size_t)warp * HID + l * 8;
        *(float4*)(ag)     = make_float4(r[0], r[1], r[2], r[3]);
        *(float4*)(ag + 4) = make_float4(r[4], r[5], r[6], r[7]);
#pragma unroll
        for (int i = 0; i < 8; i++) {
            atomicAdd(&ssum[l * 8 + i], r[i]);
            atomicAdd(&ssq [l * 8 + i], r[i] * r[i]);
        }
    }
    __syncthreads();
    if (tid < 64) {
        atomicAdd(&g_stats[tid],      ssum[tid]);
        atomicAdd(&g_stats[64 + tid], ssq[tid]);
    }
}

// ---------------- BN coefficients (also re-zeroes stats for next layer) ---
__global__ void k_bn_coef(const float* __restrict__ g, const float* __restrict__ bt) {
    int j = threadIdx.x;
    if (j >= HID) return;
    const float invN = 1.0f / (float)N_NODES;
    float mu  = g_stats[j] * invN;
    float var = g_stats[HID + j] * invN - mu * mu;
    float sc  = rsqrtf(var + EPS) * g[j];
    g_bnc[j]       = sc;
    g_bnc[HID + j] = bt[j] - mu * sc;
    g_stats[j] = 0.0f;
    g_stats[HID + j] = 0.0f;
}

// ---------------- MLP head (BN+ReLU fused on input) ----------------------
__global__ void k_mlp(const float* __restrict__ lw1, const float* __restrict__ lb1,
                      const float* __restrict__ lw2, const float* __restrict__ lb2,
                      float* __restrict__ out) {
    __shared__ float sW1[64 * 32];
    __shared__ float sW2[32];
    __shared__ float sB1[32];
    __shared__ float sSc[64], sSh[64];
    __shared__ float sB2;
    for (int i = threadIdx.x; i < 64 * 32; i += blockDim.x) sW1[i] = lw1[i];
    if (threadIdx.x < 32) { sW2[threadIdx.x] = lw2[threadIdx.x]; sB1[threadIdx.x] = lb1[threadIdx.x]; }
    if (threadIdx.x < 64) { sSc[threadIdx.x] = g_bnc[threadIdx.x]; sSh[threadIdx.x] = g_bnc[64 + threadIdx.x]; }
    if (threadIdx.x == 0) sB2 = lb2[0];
    __syncthreads();

    int n = blockIdx.x * blockDim.x + threadIdx.x;
    if (n >= N_NODES) return;

    float t[32];
#pragma unroll
    for (int j = 0; j < 32; j++) t[j] = sB1[j];
    const float* a = g_agg + (size_t)n * HID;
    for (int k = 0; k < 64; k++) {
        float v = fmaxf(a[k] * sSc[k] + sSh[k], 0.f);
#pragma unroll
        for (int j = 0; j < 32; j++) t[j] += v * sW1[k * 32 + j];
    }
    float o = sB2;
#pragma unroll
    for (int j = 0; j < 32; j++) {
        float r = t[j] > 0.0f ? t[j] : 0.0f;
        o += r * sW2[j];
    }
    out[n] = o;
}

// ---------------- driver --------------------------------------------------
extern "C" void kernel_launch(void* const* d_in, const int* in_sizes, int n_in,
                              void* d_out, int out_size) {
    const float* x   = (const float*)d_in[0];
    const int*   ei  = (const int*)d_in[1];     // JAX downgrades int64->int32
    int E = in_sizes[1] / 2;
    const int* src = ei;
    const int* dst = ei + E;

    const float* W[3]  = { (const float*)d_in[2],  (const float*)d_in[6],  (const float*)d_in[10] };
    const float* B[3]  = { (const float*)d_in[3],  (const float*)d_in[7],  (const float*)d_in[11] };
    const float* G[3]  = { (const float*)d_in[4],  (const float*)d_in[8],  (const float*)d_in[12] };
    const float* BT[3] = { (const float*)d_in[5],  (const float*)d_in[9],  (const float*)d_in[13] };
    const float* lw1 = (const float*)d_in[14];
    const float* lb1 = (const float*)d_in[15];
    const float* lw2 = (const float*)d_in[16];
    const float* lb2 = (const float*)d_in[17];
    float* out = (float*)d_out;

    // CSR build (per launch; edge fill order nondeterministic -> only last-ulp
    // variation in fp32 sums, well inside 1e-3 tolerance)
    k_zero_idx  <<<(N_NODES + 255) / 256, 256>>>();
    k_count_deg <<<(E + 255) / 256, 256>>>(dst, E);
    k_finish_deg<<<(N_NODES + 255) / 256, 256>>>();
    k_scan_p1   <<<SCAN_NBLK, 256>>>();
    k_scan_p2   <<<1, 128>>>();
    k_scan_p3   <<<SCAN_NBLK, 256>>>(E);
    k_fill      <<<(E + 255) / 256, 256>>>(src, dst, E);

    int gemm_grid = (N_NODES + 127) / 128;
    int agg_grid  = (N_NODES * 32 + 255) / 256;
    for (int l = 0; l < 3; l++) {
        int fi = (l == 0) ? 128 : HID;
        k_gemm_fused<<<gemm_grid, 256>>>(x, W[l], fi, l == 0 ? 0 : 1);
        k_aggregate<<<agg_grid, 256>>>(B[l]);
        k_bn_coef<<<1, HID>>>(G[l], BT[l]);
    }

    k_mlp<<<(N_NODES + 255) / 256, 256>>>(lw1, lb1, lw2, lb2, out);
}